// round 1
// baseline (speedup 1.0000x reference)
#include <cuda_runtime.h>

// CountVectorizer == per-row bincount over vocab followed by counts @ W + b.
// Since counts[b] has exactly SEQ non-zeros (with multiplicity), this is just
//   out[b, :] = bias + sum_t W[token_ids[b, t], :]
// i.e. an embedding gather-sum. Memory-bound: ~105 MB of L2-side gather
// traffic, ~53 MB DRAM (W fits in L2).

#define CV_BATCH 1024
#define CV_SEQ   200
#define CV_D     128          // d_model
#define CV_D4    (CV_D / 4)   // 32 float4 per row
#define CV_GROUPS 8           // token groups per CTA

__global__ __launch_bounds__(256, 8)
void count_vectorizer_kernel(const int* __restrict__ token_ids,
                             const float4* __restrict__ W4,
                             const float* __restrict__ bias,
                             float4* __restrict__ out4)
{
    __shared__ int s_ids[CV_SEQ];
    __shared__ float4 s_acc[CV_GROUPS][CV_D4];

    const int b = blockIdx.x;

    // Stage this row's token ids.
    for (int i = threadIdx.x; i < CV_SEQ; i += blockDim.x)
        s_ids[i] = token_ids[b * CV_SEQ + i];
    __syncthreads();

    const int lane = threadIdx.x & 31;   // which float4 of the 128-wide row
    const int grp  = threadIdx.x >> 5;   // token group 0..7

    float4 acc = make_float4(0.f, 0.f, 0.f, 0.f);

    // 200 / 8 = 25 iterations, each an independent LDG.128 (good MLP).
    #pragma unroll 5
    for (int t = grp; t < CV_SEQ; t += CV_GROUPS) {
        const float4 v = W4[(size_t)s_ids[t] * CV_D4 + lane];
        acc.x += v.x; acc.y += v.y; acc.z += v.z; acc.w += v.w;
    }

    s_acc[grp][lane] = acc;
    __syncthreads();

    if (grp == 0) {
        float4 a = s_acc[0][lane];
        #pragma unroll
        for (int g = 1; g < CV_GROUPS; g++) {
            const float4 v = s_acc[g][lane];
            a.x += v.x; a.y += v.y; a.z += v.z; a.w += v.w;
        }
        const float4 bb = reinterpret_cast<const float4*>(bias)[lane];
        a.x += bb.x; a.y += bb.y; a.z += bb.z; a.w += bb.w;
        out4[(size_t)b * CV_D4 + lane] = a;
    }
}

extern "C" void kernel_launch(void* const* d_in, const int* in_sizes, int n_in,
                              void* d_out, int out_size)
{
    const int*   token_ids = (const int*)d_in[0];      // [1024, 200] int32
    const float* W         = (const float*)d_in[1];    // [100000, 128] f32
    const float* bias      = (const float*)d_in[2];    // [128] f32
    float*       out       = (float*)d_out;            // [1024, 128] f32

    (void)in_sizes; (void)n_in; (void)out_size;

    count_vectorizer_kernel<<<CV_BATCH, 256>>>(
        token_ids,
        reinterpret_cast<const float4*>(W),
        bias,
        reinterpret_cast<float4*>(out));
}